// round 3
// baseline (speedup 1.0000x reference)
#include <cuda_runtime.h>
#include <math.h>

// ---------------------------------------------------------------------------
// Net_76690936037575: var/con 2->128->128 MLPs, scatter to node buffer,
// gather by assoc_var, 3x (128x128 GEMM + ReLU), 128->1 + sigmoid.
// Round 2: fp32 SIMT register-tiled GEMMs; assoc indices are int32 (JAX x64
// disabled downcasts the reference's int64 arrays).
// ---------------------------------------------------------------------------

#define TILE_M 128
#define PITCH  132   // smem pitch for transposed activation tiles [k][m]

// Node embedding scratch: n_nodes (1e6) x 128 fp32 = 512 MB, static device mem.
__device__ float g_xbuf[128u * 1000000u];

// ---------------------------------------------------------------------------
// Register-tiled GEMM over one 128x128 tile:
//   out[m][n] = bias[n] + sum_k A[k][m] * W[k][n]
// A: smem, transposed activations, pitch PITCH.  W: smem, row-major [k][n], pitch 128.
// Thread mapping: tm = (tid&15)*8 (m strip), tn = (tid>>4)*8 (n strip).
// ---------------------------------------------------------------------------
__device__ __forceinline__ void gemm_tile(const float* __restrict__ A,
                                          const float* __restrict__ Ws,
                                          const float* __restrict__ bias_g,
                                          float acc[8][8], int tid)
{
    const int tm = (tid & 15) * 8;
    const int tn = (tid >> 4) * 8;

    float bj[8];
#pragma unroll
    for (int j = 0; j < 8; j++) bj[j] = __ldg(&bias_g[tn + j]);
#pragma unroll
    for (int i = 0; i < 8; i++)
#pragma unroll
        for (int j = 0; j < 8; j++) acc[i][j] = bj[j];

#pragma unroll 4
    for (int k = 0; k < 128; k++) {
        float4 a0 = *(const float4*)&A[k * PITCH + tm];
        float4 a1 = *(const float4*)&A[k * PITCH + tm + 4];
        float4 w0 = *(const float4*)&Ws[k * 128 + tn];
        float4 w1 = *(const float4*)&Ws[k * 128 + tn + 4];
        float a[8] = {a0.x, a0.y, a0.z, a0.w, a1.x, a1.y, a1.z, a1.w};
        float w[8] = {w0.x, w0.y, w0.z, w0.w, w1.x, w1.y, w1.z, w1.w};
#pragma unroll
        for (int i = 0; i < 8; i++)
#pragma unroll
            for (int j = 0; j < 8; j++)
                acc[i][j] = fmaf(a[i], w[j], acc[i][j]);
    }
}

// Store acc (with ReLU) into transposed smem tile D[n][m], pitch PITCH.
__device__ __forceinline__ void store_tile_relu_T(float* __restrict__ D,
                                                  const float acc[8][8], int tid)
{
    const int tm = (tid & 15) * 8;
    const int tn = (tid >> 4) * 8;
#pragma unroll
    for (int j = 0; j < 8; j++) {
        float4 lo = make_float4(fmaxf(acc[0][j], 0.f), fmaxf(acc[1][j], 0.f),
                                fmaxf(acc[2][j], 0.f), fmaxf(acc[3][j], 0.f));
        float4 hi = make_float4(fmaxf(acc[4][j], 0.f), fmaxf(acc[5][j], 0.f),
                                fmaxf(acc[6][j], 0.f), fmaxf(acc[7][j], 0.f));
        float* dst = &D[(tn + j) * PITCH + tm];
        *(float4*)dst       = lo;
        *(float4*)(dst + 4) = hi;
    }
}

// ---------------------------------------------------------------------------
// Kernel A/B: one tile of rows -> mlp2(feats) -> scatter to g_xbuf[assoc[row]].
//   h = relu(f @ W1[2,128] + b1);  emb = h @ W2[128,128] + b2  (no relu)
// smem: H[128][PITCH] (transposed h), Ws[128][128], F[128][2]
// ---------------------------------------------------------------------------
extern "C" __global__ void __launch_bounds__(256)
mlp2_scatter_kernel(const float* __restrict__ feats,
                    const int* __restrict__ assoc,
                    const float* __restrict__ W1g, const float* __restrict__ b1g,
                    const float* __restrict__ W2g, const float* __restrict__ b2g,
                    int n)
{
    extern __shared__ float sm[];
    float* H  = sm;                       // 128*PITCH
    float* Ws = sm + 128 * PITCH;         // 128*128
    float* F  = Ws + 128 * 128;           // 128*2

    const int tid = threadIdx.x;
    const int m0  = blockIdx.x * TILE_M;

    // Stage W2 (64 KB) into smem.
    for (int i = tid; i < 128 * 128 / 4; i += blockDim.x)
        ((float4*)Ws)[i] = ((const float4*)W2g)[i];

    // Stage the 2 input features per row.
    if (tid < TILE_M) {
        int row = m0 + tid;
        float2 f = make_float2(0.f, 0.f);
        if (row < n) f = ((const float2*)feats)[row];
        F[tid * 2]     = f.x;
        F[tid * 2 + 1] = f.y;
    }
    __syncthreads();

    // Layer 1: H[k][m] = relu(f0*W1[0][k] + f1*W1[1][k] + b1[k])
    for (int idx = tid; idx < 128 * 128; idx += blockDim.x) {
        int kf = idx >> 7;
        int m  = idx & 127;
        float h = fmaf(F[m * 2], __ldg(&W1g[kf]),
                  fmaf(F[m * 2 + 1], __ldg(&W1g[128 + kf]), __ldg(&b1g[kf])));
        H[kf * PITCH + m] = fmaxf(h, 0.f);
    }
    __syncthreads();

    // Layer 2: emb = H^T @ W2 + b2, scatter rows to g_xbuf[assoc[row]].
    float acc[8][8];
    gemm_tile(H, Ws, b2g, acc, tid);

    const int tm = (tid & 15) * 8;
    const int tn = (tid >> 4) * 8;
#pragma unroll
    for (int i = 0; i < 8; i++) {
        int row = m0 + tm + i;
        if (row < n) {
            int node = assoc[row];
            float* dst = g_xbuf + (size_t)node * 128 + tn;
            *(float4*)dst       = make_float4(acc[i][0], acc[i][1], acc[i][2], acc[i][3]);
            *(float4*)(dst + 4) = make_float4(acc[i][4], acc[i][5], acc[i][6], acc[i][7]);
        }
    }
}

// ---------------------------------------------------------------------------
// Kernel C: gather g_xbuf[assoc_var[row]], 3x (GEMM+ReLU) in smem, final
// 128->1 dot + sigmoid.
// smem: A[128][PITCH], B[128][PITCH], Ws[128][128]
// ---------------------------------------------------------------------------
extern "C" __global__ void __launch_bounds__(256)
head_kernel(const int* __restrict__ assoc,
            const float* __restrict__ W1g, const float* __restrict__ b1g,
            const float* __restrict__ W2g, const float* __restrict__ b2g,
            const float* __restrict__ W3g, const float* __restrict__ b3g,
            const float* __restrict__ W4g, const float* __restrict__ b4g,
            float* __restrict__ out, int n)
{
    extern __shared__ float sm[];
    float* A  = sm;                       // 128*PITCH
    float* B  = sm + 128 * PITCH;         // 128*PITCH
    float* Ws = sm + 2 * 128 * PITCH;     // 128*128
    __shared__ int nodes[TILE_M];

    const int tid = threadIdx.x;
    const int m0  = blockIdx.x * TILE_M;

    if (tid < TILE_M) {
        int row = m0 + tid;
        nodes[tid] = (row < n) ? assoc[row] : 0;
    }
    // Stage W1.
    for (int i = tid; i < 128 * 128 / 4; i += blockDim.x)
        ((float4*)Ws)[i] = ((const float4*)W1g)[i];
    __syncthreads();

    // Gather rows, transposed into A[k][m].
    for (int idx = tid; idx < 128 * 32; idx += blockDim.x) {
        int m = idx >> 5;
        int q = idx & 31;
        float4 v = ((const float4*)(g_xbuf + (size_t)nodes[m] * 128))[q];
        int k = q * 4;
        A[(k + 0) * PITCH + m] = v.x;
        A[(k + 1) * PITCH + m] = v.y;
        A[(k + 2) * PITCH + m] = v.z;
        A[(k + 3) * PITCH + m] = v.w;
    }
    __syncthreads();

    float acc[8][8];

    // Layer 1: A -> B
    gemm_tile(A, Ws, b1g, acc, tid);
    store_tile_relu_T(B, acc, tid);
    __syncthreads();
    for (int i = tid; i < 128 * 128 / 4; i += blockDim.x)
        ((float4*)Ws)[i] = ((const float4*)W2g)[i];
    __syncthreads();

    // Layer 2: B -> A
    gemm_tile(B, Ws, b2g, acc, tid);
    store_tile_relu_T(A, acc, tid);
    __syncthreads();
    for (int i = tid; i < 128 * 128 / 4; i += blockDim.x)
        ((float4*)Ws)[i] = ((const float4*)W3g)[i];
    __syncthreads();

    // Layer 3: A -> B
    gemm_tile(A, Ws, b3g, acc, tid);
    store_tile_relu_T(B, acc, tid);
    __syncthreads();

    // Stage W4 (128 floats) into Ws[0..127].
    if (tid < 128) Ws[tid] = __ldg(&W4g[tid]);
    __syncthreads();

    // Final: out[row] = sigmoid(dot(B[:,m], W4) + b4)
    if (tid < TILE_M) {
        int row = m0 + tid;
        if (row < n) {
            float s = __ldg(&b4g[0]);
#pragma unroll 8
            for (int k = 0; k < 128; k++)
                s = fmaf(B[k * PITCH + tid], Ws[k], s);
            out[row] = 1.f / (1.f + expf(-s));
        }
    }
}

// ---------------------------------------------------------------------------
// Launch
// ---------------------------------------------------------------------------
extern "C" void kernel_launch(void* const* d_in, const int* in_sizes, int n_in,
                              void* d_out, int out_size)
{
    (void)n_in; (void)out_size;
    const float* varf      = (const float*)d_in[0];
    const float* conf      = (const float*)d_in[1];
    /* d_in[2] = node_types (unused) */
    const int*   assoc_var = (const int*)d_in[3];   // int32: JAX x64 disabled
    const int*   assoc_con = (const int*)d_in[4];
    const float* vW1 = (const float*)d_in[5];
    const float* vb1 = (const float*)d_in[6];
    const float* vW2 = (const float*)d_in[7];
    const float* vb2 = (const float*)d_in[8];
    const float* cW1 = (const float*)d_in[9];
    const float* cb1 = (const float*)d_in[10];
    const float* cW2 = (const float*)d_in[11];
    const float* cb2 = (const float*)d_in[12];
    const float* W1  = (const float*)d_in[13];
    const float* b1  = (const float*)d_in[14];
    const float* W2  = (const float*)d_in[15];
    const float* b2  = (const float*)d_in[16];
    const float* W3  = (const float*)d_in[17];
    const float* b3  = (const float*)d_in[18];
    const float* W4  = (const float*)d_in[19];
    const float* b4  = (const float*)d_in[20];
    float* out = (float*)d_out;

    const int n_var = in_sizes[0] / 2;
    const int n_con = in_sizes[1] / 2;

    const int smem_mlp  = (128 * PITCH + 128 * 128 + 256) * 4;      // 134144 B
    const int smem_head = (2 * 128 * PITCH + 128 * 128) * 4;        // 200704 B

    cudaFuncSetAttribute(mlp2_scatter_kernel,
                         cudaFuncAttributeMaxDynamicSharedMemorySize, smem_mlp);
    cudaFuncSetAttribute(head_kernel,
                         cudaFuncAttributeMaxDynamicSharedMemorySize, smem_head);

    const int gv = (n_var + TILE_M - 1) / TILE_M;
    const int gc = (n_con + TILE_M - 1) / TILE_M;

    // var embeddings first, con second (con overwrites on overlap, matching
    // x.at[assoc_var].set(n); x.at[assoc_con].set(e) ordering).
    mlp2_scatter_kernel<<<gv, 256, smem_mlp>>>(varf, assoc_var, vW1, vb1, vW2, vb2, n_var);
    mlp2_scatter_kernel<<<gc, 256, smem_mlp>>>(conf, assoc_con, cW1, cb1, cW2, cb2, n_con);
    head_kernel<<<gv, 256, smem_head>>>(assoc_var, W1, b1, W2, b2, W3, b3, W4, b4, out, n_var);
}

// round 6
// speedup vs baseline: 2.3903x; 2.3903x over previous
#include <cuda_runtime.h>
#include <math.h>
#include <stdint.h>

// ---------------------------------------------------------------------------
// Net_76690936037575 — mma.sync tf32 version (tcgen05 not available: harness
// PTX target is compute_103, arch-conditional features rejected by ptxas).
// All GEMMs are 128x128x128 per CTA: C = A @ W (+bias, opt ReLU), computed by
// 8 warps with m16n8k8 tf32 mma.sync, fp32 accumulate in registers.
// A[m][k], B=W^T[n][k] row-major in SMEM, pitch 132 (conflict-free fragments).
// ---------------------------------------------------------------------------

#define PITCH 132

// Node embeddings: 1e6 x 128 fp32 (stored tf32-rounded). 512 MB static.
__device__ float g_xbuf[128u * 1000000u];
// Transposed tf32 weights, pitch 132: 0=vW2^T 1=cW2^T 2=W1^T 3=W2^T 4=W3^T
__device__ float g_wT[5][128 * PITCH];

__device__ __forceinline__ float cvt_tf32f(float x) {
    uint32_t r;
    asm("cvt.rna.tf32.f32 %0, %1;" : "=r"(r) : "f"(x));
    return __uint_as_float(r);
}

__device__ __forceinline__ void mma8(float* d, const uint32_t* a, const uint32_t* b) {
    asm volatile("mma.sync.aligned.m16n8k8.row.col.f32.tf32.tf32.f32 "
                 "{%0,%1,%2,%3}, {%4,%5,%6,%7}, {%8,%9}, {%0,%1,%2,%3};"
                 : "+f"(d[0]), "+f"(d[1]), "+f"(d[2]), "+f"(d[3])
                 : "r"(a[0]), "r"(a[1]), "r"(a[2]), "r"(a[3]),
                   "r"(b[0]), "r"(b[1]));
}

// 128x128x128 GEMM: acc[mt][nt][c] += A @ B^T over full K=128.
// Warp w covers m in [m0w, m0w+32), n in [n0w, n0w+64).
// Fragment rows: a: (g, g+8) x cols (tg, tg+4);  b: rows (tg, tg+4) x col g.
__device__ __forceinline__ void gemm128(const float* __restrict__ As,
                                        const float* __restrict__ Bs,
                                        float acc[2][8][4],
                                        int lane, int m0w, int n0w)
{
    const int g = lane >> 2, tg = lane & 3;
    const float* Abase = As + (m0w + g) * PITCH + tg;
    const float* Bbase = Bs + (n0w + g) * PITCH + tg;
#pragma unroll
    for (int kt = 0; kt < 16; kt++) {
        const int k0 = kt * 8;
        uint32_t a[2][4], b[8][2];
#pragma unroll
        for (int mt = 0; mt < 2; mt++) {
            const float* p = Abase + mt * 16 * PITCH + k0;
            a[mt][0] = __float_as_uint(p[0]);
            a[mt][1] = __float_as_uint(p[8 * PITCH]);
            a[mt][2] = __float_as_uint(p[4]);
            a[mt][3] = __float_as_uint(p[8 * PITCH + 4]);
        }
#pragma unroll
        for (int nt = 0; nt < 8; nt++) {
            const float* p = Bbase + nt * 8 * PITCH + k0;
            b[nt][0] = __float_as_uint(p[0]);
            b[nt][1] = __float_as_uint(p[4]);
        }
#pragma unroll
        for (int mt = 0; mt < 2; mt++)
#pragma unroll
            for (int nt = 0; nt < 8; nt++)
                mma8(acc[mt][nt], a[mt], b[nt]);
    }
}

__device__ __forceinline__ void stageB(float* __restrict__ Bs,
                                       const float* __restrict__ wt, int tid)
{
    const float4* src = (const float4*)wt;
    float4* dst = (float4*)Bs;
#pragma unroll 4
    for (int i = tid; i < 128 * PITCH / 4; i += 256) dst[i] = src[i];
}

// ---------------------------------------------------------------------------
// Prep: g_wT[w][n*PITCH + k] = tf32(W[k*128+n]).
// ---------------------------------------------------------------------------
extern "C" __global__ void prep_kernel(const float* __restrict__ vW2, const float* __restrict__ cW2,
                                       const float* __restrict__ W1, const float* __restrict__ W2,
                                       const float* __restrict__ W3)
{
    int idx = blockIdx.x * 256 + threadIdx.x;
    if (idx >= 5 * 16384) return;
    int w = idx >> 14, e = idx & 16383;
    int nn = e >> 7, k = e & 127;
    const float* src = (w == 0) ? vW2 : (w == 1) ? cW2 : (w == 2) ? W1 : (w == 3) ? W2 : W3;
    g_wT[w][nn * PITCH + k] = cvt_tf32f(src[k * 128 + nn]);
}

// ---------------------------------------------------------------------------
// mlp2_scatter: h = relu(f @ W1[2,128] + b1) (fp32, then tf32-round);
//               emb = h @ W2 + b2 -> scatter tf32-rounded to g_xbuf[assoc].
// ---------------------------------------------------------------------------
extern "C" __global__ void __launch_bounds__(256)
mlp2_scatter_kernel(const float* __restrict__ feats, const int* __restrict__ assoc,
                    const float* __restrict__ W1g, const float* __restrict__ b1g,
                    const float* __restrict__ b2g, int n, int widx)
{
    extern __shared__ float sm[];
    float* A    = sm;                        // 128*PITCH
    float* B    = sm + 128 * PITCH;          // 128*PITCH
    float* misc = sm + 2 * 128 * PITCH;
    float* F0  = misc;          // 128
    float* F1  = misc + 128;    // 128
    float* W1s = misc + 256;    // 256
    float* b1s = misc + 512;    // 128
    float* b2s = misc + 640;    // 128
    int*   nodes = (int*)(misc + 768);  // 128

    const int tid = threadIdx.x, lane = tid & 31, w = tid >> 5;
    const int m0 = blockIdx.x * 128;
    const int m0w = (w & 3) * 32, n0w = (w >> 2) * 64;

    if (tid < 256) W1s[tid] = W1g[tid];
    if (tid < 128) {
        b1s[tid] = b1g[tid];
        b2s[tid] = b2g[tid];
        int r = m0 + tid;
        nodes[tid] = (r < n) ? assoc[r] : 0;
        float2 f = (r < n) ? ((const float2*)feats)[r] : make_float2(0.f, 0.f);
        F0[tid] = f.x; F1[tid] = f.y;
    }
    stageB(B, g_wT[widx], tid);
    __syncthreads();

    // Layer 1 (exact fp32, tf32-rounded output) -> A[m][k]
    for (int idx = tid; idx < 4096; idx += 256) {
        int m = idx >> 5, q = idx & 31, k0 = q * 4;
        float f0 = F0[m], f1 = F1[m];
        float4 pv;
        pv.x = cvt_tf32f(fmaxf(fmaf(f0, W1s[k0+0], fmaf(f1, W1s[128+k0+0], b1s[k0+0])), 0.f));
        pv.y = cvt_tf32f(fmaxf(fmaf(f0, W1s[k0+1], fmaf(f1, W1s[128+k0+1], b1s[k0+1])), 0.f));
        pv.z = cvt_tf32f(fmaxf(fmaf(f0, W1s[k0+2], fmaf(f1, W1s[128+k0+2], b1s[k0+2])), 0.f));
        pv.w = cvt_tf32f(fmaxf(fmaf(f0, W1s[k0+3], fmaf(f1, W1s[128+k0+3], b1s[k0+3])), 0.f));
        *(float4*)(A + m * PITCH + k0) = pv;
    }
    __syncthreads();

    float acc[2][8][4];
#pragma unroll
    for (int mt = 0; mt < 2; mt++)
#pragma unroll
        for (int nt = 0; nt < 8; nt++)
#pragma unroll
            for (int c = 0; c < 4; c++) acc[mt][nt][c] = 0.f;

    gemm128(A, B, acc, lane, m0w, n0w);

    // Epilogue: +b2, tf32-round, scatter rows to g_xbuf.
    const int g = lane >> 2, tg = lane & 3;
#pragma unroll
    for (int mt = 0; mt < 2; mt++) {
        int row0 = m0w + 16 * mt + g;
        int row1 = row0 + 8;
        bool v0 = (m0 + row0 < n), v1 = (m0 + row1 < n);
        float* d0 = g_xbuf + (size_t)nodes[row0] * 128;
        float* d1 = g_xbuf + (size_t)nodes[row1] * 128;
#pragma unroll
        for (int j = 0; j < 8; j++) {
            int col = n0w + 8 * j + 2 * tg;
            if (v0) {
                float2 pv = make_float2(cvt_tf32f(acc[mt][j][0] + b2s[col]),
                                        cvt_tf32f(acc[mt][j][1] + b2s[col + 1]));
                *(float2*)(d0 + col) = pv;
            }
            if (v1) {
                float2 pv = make_float2(cvt_tf32f(acc[mt][j][2] + b2s[col]),
                                        cvt_tf32f(acc[mt][j][3] + b2s[col + 1]));
                *(float2*)(d1 + col) = pv;
            }
        }
    }
}

// ---------------------------------------------------------------------------
// head: gather -> 3x (GEMM+bias+ReLU) -> dot W4 + b4 -> sigmoid
// ---------------------------------------------------------------------------
extern "C" __global__ void __launch_bounds__(256)
head_kernel(const int* __restrict__ assoc,
            const float* __restrict__ b1g, const float* __restrict__ b2g,
            const float* __restrict__ b3g, const float* __restrict__ W4g,
            const float* __restrict__ b4g, float* __restrict__ out, int n)
{
    extern __shared__ float sm[];
    float* A    = sm;
    float* B    = sm + 128 * PITCH;
    float* misc = sm + 2 * 128 * PITCH;
    // misc: [0]b1 [128]b2 [256]b3 [384]W4 [512]part(256) [768]nodes(int 128)
    float* W4s  = misc + 384;
    float* part = misc + 512;
    int*   nodes = (int*)(misc + 768);

    const int tid = threadIdx.x, lane = tid & 31, w = tid >> 5;
    const int m0 = blockIdx.x * 128;
    const int m0w = (w & 3) * 32, n0w = (w >> 2) * 64;
    const int g = lane >> 2, tg = lane & 3;

    if (tid < 128) {
        misc[tid]       = b1g[tid];
        misc[128 + tid] = b2g[tid];
        misc[256 + tid] = b3g[tid];
        W4s[tid]        = W4g[tid];
        int r = m0 + tid;
        nodes[tid] = (r < n) ? assoc[r] : 0;
    }
    __syncthreads();

    // Gather A[m][k] from g_xbuf (already tf32-rounded).
    for (int idx = tid; idx < 4096; idx += 256) {
        int m = idx >> 5, q = idx & 31;
        float4 v = ((const float4*)(g_xbuf + (size_t)nodes[m] * 128))[q];
        *(float4*)(A + m * PITCH + q * 4) = v;
    }
    stageB(B, g_wT[2], tid);
    __syncthreads();

#pragma unroll 1
    for (int lyr = 0; lyr < 3; lyr++) {
        float acc[2][8][4];
#pragma unroll
        for (int mt = 0; mt < 2; mt++)
#pragma unroll
            for (int nt = 0; nt < 8; nt++)
#pragma unroll
                for (int c = 0; c < 4; c++) acc[mt][nt][c] = 0.f;

        gemm128(A, B, acc, lane, m0w, n0w);
        __syncthreads();   // all warps done reading A and B

        const float* bias = misc + lyr * 128;
        if (lyr < 2) {
            // relu + bias + tf32 -> A (in place), restage next weights -> B
#pragma unroll
            for (int mt = 0; mt < 2; mt++) {
                int row0 = m0w + 16 * mt + g;
#pragma unroll
                for (int j = 0; j < 8; j++) {
                    int col = n0w + 8 * j + 2 * tg;
                    float2 p0 = make_float2(cvt_tf32f(fmaxf(acc[mt][j][0] + bias[col], 0.f)),
                                            cvt_tf32f(fmaxf(acc[mt][j][1] + bias[col + 1], 0.f)));
                    float2 p1 = make_float2(cvt_tf32f(fmaxf(acc[mt][j][2] + bias[col], 0.f)),
                                            cvt_tf32f(fmaxf(acc[mt][j][3] + bias[col + 1], 0.f)));
                    *(float2*)(A + row0 * PITCH + col) = p0;
                    *(float2*)(A + (row0 + 8) * PITCH + col) = p1;
                }
            }
            stageB(B, g_wT[3 + lyr], tid);
            __syncthreads();
        } else {
            // Final: relu + bias, dot with W4, reduce over the 4-lane group.
#pragma unroll
            for (int mt = 0; mt < 2; mt++) {
                float p0 = 0.f, p1 = 0.f;
#pragma unroll
                for (int j = 0; j < 8; j++) {
                    int col = n0w + 8 * j + 2 * tg;
                    p0 = fmaf(fmaxf(acc[mt][j][0] + bias[col], 0.f),     W4s[col],     p0);
                    p0 = fmaf(fmaxf(acc[mt][j][1] + bias[col + 1], 0.f), W4s[col + 1], p0);
                    p1 = fmaf(fmaxf(acc[mt][j][2] + bias[col], 0.f),     W4s[col],     p1);
                    p1 = fmaf(fmaxf(acc[mt][j][3] + bias[col + 1], 0.f), W4s[col + 1], p1);
                }
                p0 += __shfl_xor_sync(0xffffffffu, p0, 1);
                p0 += __shfl_xor_sync(0xffffffffu, p0, 2);
                p1 += __shfl_xor_sync(0xffffffffu, p1, 1);
                p1 += __shfl_xor_sync(0xffffffffu, p1, 2);
                if (tg == 0) {
                    int row0 = m0w + 16 * mt + g;
                    part[(w >> 2) * 128 + row0] = p0;
                    part[(w >> 2) * 128 + row0 + 8] = p1;
                }
            }
            __syncthreads();
            if (tid < 128) {
                int row = m0 + tid;
                if (row < n) {
                    float s = part[tid] + part[128 + tid] + __ldg(&b4g[0]);
                    out[row] = 1.f / (1.f + expf(-s));
                }
            }
        }
    }
}

// ---------------------------------------------------------------------------
// Launch
// ---------------------------------------------------------------------------
extern "C" void kernel_launch(void* const* d_in, const int* in_sizes, int n_in,
                              void* d_out, int out_size)
{
    (void)n_in; (void)out_size;
    const float* varf      = (const float*)d_in[0];
    const float* conf      = (const float*)d_in[1];
    const int*   assoc_var = (const int*)d_in[3];
    const int*   assoc_con = (const int*)d_in[4];
    const float* vW1 = (const float*)d_in[5];
    const float* vb1 = (const float*)d_in[6];
    const float* vW2 = (const float*)d_in[7];
    const float* vb2 = (const float*)d_in[8];
    const float* cW1 = (const float*)d_in[9];
    const float* cb1 = (const float*)d_in[10];
    const float* cW2 = (const float*)d_in[11];
    const float* cb2 = (const float*)d_in[12];
    const float* W1  = (const float*)d_in[13];
    const float* b1  = (const float*)d_in[14];
    const float* W2  = (const float*)d_in[15];
    const float* b2  = (const float*)d_in[16];
    const float* W3  = (const float*)d_in[17];
    const float* b3  = (const float*)d_in[18];
    const float* W4  = (const float*)d_in[19];
    const float* b4  = (const float*)d_in[20];
    float* out = (float*)d_out;

    const int n_var = in_sizes[0] / 2;
    const int n_con = in_sizes[1] / 2;

    const int smem_bytes = (2 * 128 * PITCH + 1024) * 4;   // ~139 KB

    cudaFuncSetAttribute(mlp2_scatter_kernel,
                         cudaFuncAttributeMaxDynamicSharedMemorySize, smem_bytes);
    cudaFuncSetAttribute(head_kernel,
                         cudaFuncAttributeMaxDynamicSharedMemorySize, smem_bytes);

    const int gv = (n_var + 127) / 128;
    const int gc = (n_con + 127) / 128;

    prep_kernel<<<(5 * 16384 + 255) / 256, 256>>>(vW2, cW2, W1, W2, W3);
    // var first, con second (con overwrites shared nodes), then head.
    mlp2_scatter_kernel<<<gv, 256, smem_bytes>>>(varf, assoc_var, vW1, vb1, vb2, n_var, 0);
    mlp2_scatter_kernel<<<gc, 256, smem_bytes>>>(conf, assoc_con, cW1, cb1, cb2, n_con, 1);
    head_kernel<<<gv, 256, smem_bytes>>>(assoc_var, b1, b2, b3, W4, b4, out, n_var);
}

// round 7
// speedup vs baseline: 2.5738x; 1.0768x over previous
#include <cuda_runtime.h>
#include <math.h>
#include <stdint.h>

// ---------------------------------------------------------------------------
// Net_76690936037575 — mma.sync tf32, M=256 tiles, 512 threads, permuted-k
// SMEM layout so all mma fragment loads are float2 (LDS.64).
// Stored column for logical k: sidx(k) = (k&~7) | ((k&3)<<1) | ((k>>2)&1).
// Then lane (g,tg) reads its (k=tg, k=tg+4) fragment pair contiguously.
// ---------------------------------------------------------------------------

#define PITCH 132

// Node embeddings: 1e6 x 128 fp32 (stored tf32-rounded). 512 MB static.
__device__ float g_xbuf[128u * 1000000u];
// Transposed + k-permuted + pitched tf32 weights: 0=vW2^T 1=cW2^T 2=W1^T 3=W2^T 4=W3^T
__device__ float g_wT[5][128 * PITCH];

__device__ __forceinline__ float cvt_tf32f(float x) {
    uint32_t r;
    asm("cvt.rna.tf32.f32 %0, %1;" : "=r"(r) : "f"(x));
    return __uint_as_float(r);
}

__device__ __forceinline__ void mma8(float* d, const uint32_t* a, const uint32_t* b) {
    asm volatile("mma.sync.aligned.m16n8k8.row.col.f32.tf32.tf32.f32 "
                 "{%0,%1,%2,%3}, {%4,%5,%6,%7}, {%8,%9}, {%0,%1,%2,%3};"
                 : "+f"(d[0]), "+f"(d[1]), "+f"(d[2]), "+f"(d[3])
                 : "r"(a[0]), "r"(a[1]), "r"(a[2]), "r"(a[3]),
                   "r"(b[0]), "r"(b[1]));
}

// 128(m-warp 32) x 64(n) x 128(k) warp GEMM over permuted-k tiles.
__device__ __forceinline__ void gemm_frag(const float* __restrict__ As,
                                          const float* __restrict__ Bs,
                                          float acc[2][8][4],
                                          int lane, int m0w, int n0w)
{
    const int g = lane >> 2, tg = lane & 3;
    const float* Ab = As + (m0w + g) * PITCH + 2 * tg;
    const float* Bb = Bs + (n0w + g) * PITCH + 2 * tg;
#pragma unroll
    for (int kt = 0; kt < 16; kt++) {
        const int k0 = kt * 8;
        float2 a00 = *(const float2*)(Ab + k0);                    // rows g, g+8 (mt 0)
        float2 a01 = *(const float2*)(Ab + 8 * PITCH + k0);
        float2 a10 = *(const float2*)(Ab + 16 * PITCH + k0);       // mt 1
        float2 a11 = *(const float2*)(Ab + 24 * PITCH + k0);
        uint32_t a[2][4];
        a[0][0] = __float_as_uint(a00.x); a[0][1] = __float_as_uint(a01.x);
        a[0][2] = __float_as_uint(a00.y); a[0][3] = __float_as_uint(a01.y);
        a[1][0] = __float_as_uint(a10.x); a[1][1] = __float_as_uint(a11.x);
        a[1][2] = __float_as_uint(a10.y); a[1][3] = __float_as_uint(a11.y);
        uint32_t b[8][2];
#pragma unroll
        for (int nt = 0; nt < 8; nt++) {
            float2 bv = *(const float2*)(Bb + nt * 8 * PITCH + k0);
            b[nt][0] = __float_as_uint(bv.x);
            b[nt][1] = __float_as_uint(bv.y);
        }
#pragma unroll
        for (int mt = 0; mt < 2; mt++)
#pragma unroll
            for (int nt = 0; nt < 8; nt++)
                mma8(acc[mt][nt], a[mt], b[nt]);
    }
}

__device__ __forceinline__ void stageB(float* __restrict__ Bs,
                                       const float* __restrict__ wt, int tid)
{
    const float4* src = (const float4*)wt;
    float4* dst = (float4*)Bs;
#pragma unroll 2
    for (int i = tid; i < 128 * PITCH / 4; i += 512) dst[i] = src[i];
}

// Interleave 8 consecutive-k values into permuted storage (2x float4).
// Stored: (h0,h4,h1,h5) at +0, (h2,h6,h3,h7) at +4.
__device__ __forceinline__ void store_perm8(float* dst, const float h[8]) {
    *(float4*)(dst)     = make_float4(h[0], h[4], h[1], h[5]);
    *(float4*)(dst + 4) = make_float4(h[2], h[6], h[3], h[7]);
}

// ---------------------------------------------------------------------------
// Prep: g_wT[w][n*PITCH + sidx(k)] = tf32(W[k*128+n]).
// ---------------------------------------------------------------------------
extern "C" __global__ void prep_kernel(const float* __restrict__ vW2, const float* __restrict__ cW2,
                                       const float* __restrict__ W1, const float* __restrict__ W2,
                                       const float* __restrict__ W3)
{
    int idx = blockIdx.x * 256 + threadIdx.x;
    if (idx >= 5 * 16384) return;
    int w = idx >> 14, e = idx & 16383;
    int nn = e >> 7, k = e & 127;
    const float* src = (w == 0) ? vW2 : (w == 1) ? cW2 : (w == 2) ? W1 : (w == 3) ? W2 : W3;
    int s = (k & ~7) | ((k & 3) << 1) | ((k >> 2) & 1);
    g_wT[w][nn * PITCH + s] = cvt_tf32f(src[k * 128 + nn]);
}

// ---------------------------------------------------------------------------
// mlp2_scatter: 256 rows/CTA. h = relu(f @ W1[2,128]+b1); emb = h@W2+b2 ->
// scatter tf32-rounded (normal layout) to g_xbuf[assoc].
// ---------------------------------------------------------------------------
extern "C" __global__ void __launch_bounds__(512, 1)
mlp2_scatter_kernel(const float* __restrict__ feats, const int* __restrict__ assoc,
                    const float* __restrict__ W1g, const float* __restrict__ b1g,
                    const float* __restrict__ b2g, int n, int widx)
{
    extern __shared__ float sm[];
    float* A    = sm;                         // 256*PITCH
    float* B    = sm + 256 * PITCH;           // 128*PITCH
    float* misc = sm + 256 * PITCH + 128 * PITCH;
    float* F0  = misc;           // 256
    float* F1  = misc + 256;     // 256
    float* W1s = misc + 512;     // 256
    float* b1s = misc + 768;     // 128
    float* b2s = misc + 896;     // 128
    int*   nodes = (int*)(misc + 1024);   // 256

    const int tid = threadIdx.x, lane = tid & 31, w = tid >> 5;
    const int m0 = blockIdx.x * 256;
    const int m0w = (w & 7) * 32, n0w = (w >> 3) * 64;

    if (tid < 256) {
        W1s[tid] = W1g[tid];
        if (tid < 128) { b1s[tid] = b1g[tid]; b2s[tid] = b2g[tid]; }
        int r = m0 + tid;
        nodes[tid] = (r < n) ? assoc[r] : 0;
        float2 f = (r < n) ? ((const float2*)feats)[r] : make_float2(0.f, 0.f);
        F0[tid] = f.x; F1[tid] = f.y;
    }
    stageB(B, g_wT[widx], tid);
    __syncthreads();

    // Layer 1 (exact fp32, tf32-rounded) -> A permuted-k
    for (int idx = tid; idx < 256 * 16; idx += 512) {
        int m = idx >> 4, k0 = (idx & 15) * 8;
        float f0 = F0[m], f1 = F1[m];
        float h[8];
#pragma unroll
        for (int f = 0; f < 8; f++)
            h[f] = cvt_tf32f(fmaxf(fmaf(f0, W1s[k0 + f], fmaf(f1, W1s[128 + k0 + f], b1s[k0 + f])), 0.f));
        store_perm8(A + m * PITCH + k0, h);
    }
    __syncthreads();

    float acc[2][8][4];
#pragma unroll
    for (int mt = 0; mt < 2; mt++)
#pragma unroll
        for (int nt = 0; nt < 8; nt++)
#pragma unroll
            for (int c = 0; c < 4; c++) acc[mt][nt][c] = 0.f;

    gemm_frag(A, B, acc, lane, m0w, n0w);

    // Epilogue: +b2, tf32-round, scatter rows (normal layout) to g_xbuf.
    const int g = lane >> 2, tg = lane & 3;
#pragma unroll
    for (int mt = 0; mt < 2; mt++) {
        int row0 = m0w + 16 * mt + g;
        int row1 = row0 + 8;
        bool v0 = (m0 + row0 < n), v1 = (m0 + row1 < n);
        float* d0 = g_xbuf + (size_t)nodes[row0] * 128;
        float* d1 = g_xbuf + (size_t)nodes[row1] * 128;
#pragma unroll
        for (int j = 0; j < 8; j++) {
            int col = n0w + 8 * j + 2 * tg;
            if (v0) {
                float2 pv = make_float2(cvt_tf32f(acc[mt][j][0] + b2s[col]),
                                        cvt_tf32f(acc[mt][j][1] + b2s[col + 1]));
                *(float2*)(d0 + col) = pv;
            }
            if (v1) {
                float2 pv = make_float2(cvt_tf32f(acc[mt][j][2] + b2s[col]),
                                        cvt_tf32f(acc[mt][j][3] + b2s[col + 1]));
                *(float2*)(d1 + col) = pv;
            }
        }
    }
}

// ---------------------------------------------------------------------------
// head: 256 rows/CTA. gather -> 3x (GEMM+bias+ReLU) -> dot W4 + b4 -> sigmoid
// ---------------------------------------------------------------------------
extern "C" __global__ void __launch_bounds__(512, 1)
head_kernel(const int* __restrict__ assoc,
            const float* __restrict__ b1g, const float* __restrict__ b2g,
            const float* __restrict__ b3g, const float* __restrict__ W4g,
            const float* __restrict__ b4g, float* __restrict__ out, int n)
{
    extern __shared__ float sm[];
    float* A    = sm;
    float* B    = sm + 256 * PITCH;
    float* misc = sm + 256 * PITCH + 128 * PITCH;
    // misc: [0]b1 [128]b2 [256]b3 [384]W4 [512]part(512) [1024]nodes(int 256)
    float* W4s  = misc + 384;
    float* part = misc + 512;
    int*   nodes = (int*)(misc + 1024);

    const int tid = threadIdx.x, lane = tid & 31, w = tid >> 5;
    const int m0 = blockIdx.x * 256;
    const int m0w = (w & 7) * 32, n0w = (w >> 3) * 64;
    const int g = lane >> 2, tg = lane & 3;

    if (tid < 256) {
        if (tid < 128) {
            misc[tid]       = b1g[tid];
            misc[128 + tid] = b2g[tid];
            misc[256 + tid] = b3g[tid];
            W4s[tid]        = W4g[tid];
        }
        int r = m0 + tid;
        nodes[tid] = (r < n) ? assoc[r] : 0;
    }
    __syncthreads();

    // Gather -> A permuted-k (g_xbuf already tf32-rounded).
    for (int idx = tid; idx < 256 * 16; idx += 512) {
        int m = idx >> 4, k0 = (idx & 15) * 8;
        const float* srcp = g_xbuf + (size_t)nodes[m] * 128 + k0;
        float4 v = *(const float4*)srcp;
        float4 u = *(const float4*)(srcp + 4);
        *(float4*)(A + m * PITCH + k0)     = make_float4(v.x, u.x, v.y, u.y);
        *(float4*)(A + m * PITCH + k0 + 4) = make_float4(v.z, u.z, v.w, u.w);
    }
    stageB(B, g_wT[2], tid);
    __syncthreads();

#pragma unroll 1
    for (int lyr = 0; lyr < 3; lyr++) {
        float acc[2][8][4];
#pragma unroll
        for (int mt = 0; mt < 2; mt++)
#pragma unroll
            for (int nt = 0; nt < 8; nt++)
#pragma unroll
                for (int c = 0; c < 4; c++) acc[mt][nt][c] = 0.f;

        gemm_frag(A, B, acc, lane, m0w, n0w);
        __syncthreads();   // all warps done reading A and B

        const float* bias = misc + lyr * 128;
        if (lyr < 2) {
            // relu + bias + tf32 -> A (in place, permuted-k layout)
            // lane tg produces f=2tg,2tg+1 of each 8-group: stored offsets
            // s(2tg), s(2tg+1):  tg<2 -> (4tg, 4tg+2); tg>=2 -> (4(tg-2)+1, 4(tg-2)+3)
            const int off1 = (tg < 2) ? 4 * tg : 4 * (tg - 2) + 1;
            const int off2 = off1 + 2;
#pragma unroll
            for (int mt = 0; mt < 2; mt++) {
                int row0 = m0w + 16 * mt + g;
                float* a0 = A + row0 * PITCH;
                float* a1 = A + (row0 + 8) * PITCH;
#pragma unroll
                for (int j = 0; j < 8; j++) {
                    int base = n0w + 8 * j;
                    int col = base + 2 * tg;
                    a0[base + off1] = cvt_tf32f(fmaxf(acc[mt][j][0] + bias[col], 0.f));
                    a0[base + off2] = cvt_tf32f(fmaxf(acc[mt][j][1] + bias[col + 1], 0.f));
                    a1[base + off1] = cvt_tf32f(fmaxf(acc[mt][j][2] + bias[col], 0.f));
                    a1[base + off2] = cvt_tf32f(fmaxf(acc[mt][j][3] + bias[col + 1], 0.f));
                }
            }
            stageB(B, g_wT[3 + lyr], tid);
            __syncthreads();
        } else {
            // Final: relu + bias, dot with W4, reduce 4-lane group.
#pragma unroll
            for (int mt = 0; mt < 2; mt++) {
                float p0 = 0.f, p1 = 0.f;
#pragma unroll
                for (int j = 0; j < 8; j++) {
                    int col = n0w + 8 * j + 2 * tg;
                    p0 = fmaf(fmaxf(acc[mt][j][0] + bias[col], 0.f),     W4s[col],     p0);
                    p0 = fmaf(fmaxf(acc[mt][j][1] + bias[col + 1], 0.f), W4s[col + 1], p0);
                    p1 = fmaf(fmaxf(acc[mt][j][2] + bias[col], 0.f),     W4s[col],     p1);
                    p1 = fmaf(fmaxf(acc[mt][j][3] + bias[col + 1], 0.f), W4s[col + 1], p1);
                }
                p0 += __shfl_xor_sync(0xffffffffu, p0, 1);
                p0 += __shfl_xor_sync(0xffffffffu, p0, 2);
                p1 += __shfl_xor_sync(0xffffffffu, p1, 1);
                p1 += __shfl_xor_sync(0xffffffffu, p1, 2);
                if (tg == 0) {
                    int row0 = m0w + 16 * mt + g;
                    part[(w >> 3) * 256 + row0]     = p0;
                    part[(w >> 3) * 256 + row0 + 8] = p1;
                }
            }
            __syncthreads();
            if (tid < 256) {
                int row = m0 + tid;
                if (row < n) {
                    float s = part[tid] + part[256 + tid] + __ldg(&b4g[0]);
                    out[row] = 1.f / (1.f + expf(-s));
                }
            }
        }
    }
}

// ---------------------------------------------------------------------------
// Launch
// ---------------------------------------------------------------------------
extern "C" void kernel_launch(void* const* d_in, const int* in_sizes, int n_in,
                              void* d_out, int out_size)
{
    (void)n_in; (void)out_size;
    const float* varf      = (const float*)d_in[0];
    const float* conf      = (const float*)d_in[1];
    const int*   assoc_var = (const int*)d_in[3];
    const int*   assoc_con = (const int*)d_in[4];
    const float* vW1 = (const float*)d_in[5];
    const float* vb1 = (const float*)d_in[6];
    const float* vW2 = (const float*)d_in[7];
    const float* vb2 = (const float*)d_in[8];
    const float* cW1 = (const float*)d_in[9];
    const float* cb1 = (const float*)d_in[10];
    const float* cW2 = (const float*)d_in[11];
    const float* cb2 = (const float*)d_in[12];
    const float* W1  = (const float*)d_in[13];
    const float* b1  = (const float*)d_in[14];
    const float* W2  = (const float*)d_in[15];
    const float* b2  = (const float*)d_in[16];
    const float* W3  = (const float*)d_in[17];
    const float* b3  = (const float*)d_in[18];
    const float* W4  = (const float*)d_in[19];
    const float* b4  = (const float*)d_in[20];
    float* out = (float*)d_out;

    const int n_var = in_sizes[0] / 2;
    const int n_con = in_sizes[1] / 2;

    // A(256*132) + B(128*132) + misc(1280 floats + 256 ints) ≈ 203 KB
    const int smem_bytes = (256 * PITCH + 128 * PITCH + 1280) * 4 + 1024;

    cudaFuncSetAttribute(mlp2_scatter_kernel,
                         cudaFuncAttributeMaxDynamicSharedMemorySize, smem_bytes);
    cudaFuncSetAttribute(head_kernel,
                         cudaFuncAttributeMaxDynamicSharedMemorySize, smem_bytes);

    const int gv = (n_var + 255) / 256;
    const int gc = (n_con + 255) / 256;

    prep_kernel<<<(5 * 16384 + 255) / 256, 256>>>(vW2, cW2, W1, W2, W3);
    // var first, con second (con overwrites shared nodes), then head.
    mlp2_scatter_kernel<<<gv, 512, smem_bytes>>>(varf, assoc_var, vW1, vb1, vb2, n_var, 0);
    mlp2_scatter_kernel<<<gc, 512, smem_bytes>>>(conf, assoc_con, cW1, cb1, cb2, n_con, 1);
    head_kernel<<<gv, 512, smem_bytes>>>(assoc_var, b1, b2, b3, W4, b4, out, n_var);
}

// round 8
// speedup vs baseline: 4.0888x; 1.5886x over previous
#include <cuda_runtime.h>
#include <cuda_bf16.h>
#include <math.h>
#include <stdint.h>

// ---------------------------------------------------------------------------
// Net_76690936037575 — bf16 mma.sync (m16n8k16), M=256 tiles, 512 threads.
// SMEM tiles hold bf16x2 words, k-permuted so every mma fragment load is one
// uint2 (8B) LDS: word w of each 8-word (16-k) group stored at
// p(w) = ((w&3)<<1) | (w>>2); lane tg then reads words {tg, tg+4} contiguously.
// g_xbuf holds node embeddings as bf16, pre-permuted (gather = straight copy).
// All scalar math (layer-1, bias, ReLU, sigmoid, W4-dot) stays fp32.
// ---------------------------------------------------------------------------

#define PW 72   // words (bf16x2) per tile row, 64 data + 8 pad

// Node embeddings: 1e6 nodes x 64 words (128 bf16), permuted layout. 256 MB.
__device__ uint32_t g_xbuf[64u * 1000000u];
// Transposed + permuted bf16x2 weights: 0=vW2^T 1=cW2^T 2=W1^T 3=W2^T 4=W3^T
__device__ uint32_t g_wB[5][128 * PW];

__device__ __forceinline__ uint32_t pack_bf16x2(float lo, float hi) {
    uint32_t r;
    asm("cvt.rn.bf16x2.f32 %0, %1, %2;" : "=r"(r) : "f"(hi), "f"(lo));
    return r;
}

__device__ __forceinline__ void mma16(float* d, const uint32_t* a, const uint32_t* b) {
    asm volatile("mma.sync.aligned.m16n8k16.row.col.f32.bf16.bf16.f32 "
                 "{%0,%1,%2,%3}, {%4,%5,%6,%7}, {%8,%9}, {%0,%1,%2,%3};"
                 : "+f"(d[0]), "+f"(d[1]), "+f"(d[2]), "+f"(d[3])
                 : "r"(a[0]), "r"(a[1]), "r"(a[2]), "r"(a[3]),
                   "r"(b[0]), "r"(b[1]));
}

// Warp GEMM 32m x 64n x 128k over permuted bf16x2 word tiles.
// acc[mt][nt][c]: c0,c1 = (row g, cols 2tg,2tg+1); c2,c3 = row g+8.
__device__ __forceinline__ void gemm_frag(const uint32_t* __restrict__ As,
                                          const uint32_t* __restrict__ Bs,
                                          float acc[2][8][4],
                                          int lane, int m0w, int n0w)
{
    const int g = lane >> 2, tg = lane & 3;
    const uint32_t* Ab = As + (m0w + g) * PW + 2 * tg;
    const uint32_t* Bb = Bs + (n0w + g) * PW + 2 * tg;
#pragma unroll
    for (int kt = 0; kt < 8; kt++) {
        const int k0 = kt * 8;   // words
        uint2 a00 = *(const uint2*)(Ab + k0);                 // row g      (mt0)
        uint2 a01 = *(const uint2*)(Ab + 8 * PW + k0);        // row g+8
        uint2 a10 = *(const uint2*)(Ab + 16 * PW + k0);       // mt1
        uint2 a11 = *(const uint2*)(Ab + 24 * PW + k0);
        uint32_t a[2][4];
        a[0][0] = a00.x; a[0][1] = a01.x; a[0][2] = a00.y; a[0][3] = a01.y;
        a[1][0] = a10.x; a[1][1] = a11.x; a[1][2] = a10.y; a[1][3] = a11.y;
        uint32_t b[8][2];
#pragma unroll
        for (int nt = 0; nt < 8; nt++) {
            uint2 bv = *(const uint2*)(Bb + nt * 8 * PW + k0);
            b[nt][0] = bv.x; b[nt][1] = bv.y;
        }
#pragma unroll
        for (int mt = 0; mt < 2; mt++)
#pragma unroll
            for (int nt = 0; nt < 8; nt++)
                mma16(acc[mt][nt], a[mt], b[nt]);
    }
}

__device__ __forceinline__ void stageB(uint32_t* __restrict__ Bs,
                                       const uint32_t* __restrict__ wt, int tid)
{
    const uint4* src = (const uint4*)wt;
    uint4* dst = (uint4*)Bs;
#pragma unroll 2
    for (int i = tid; i < 128 * PW / 4; i += 512) dst[i] = src[i];
}

// ---------------------------------------------------------------------------
// Prep: g_wB[w][n*PW + (u&~7) + p(u&7)] = bf16x2(W[2u][n], W[2u+1][n]).
// ---------------------------------------------------------------------------
extern "C" __global__ void prep_kernel(const float* __restrict__ vW2, const float* __restrict__ cW2,
                                       const float* __restrict__ W1, const float* __restrict__ W2,
                                       const float* __restrict__ W3)
{
    int idx = blockIdx.x * 256 + threadIdx.x;
    if (idx >= 5 * 128 * 64) return;
    int w = idx >> 13, e = idx & 8191;
    int nn = e >> 6, u = e & 63;
    const float* src = (w == 0) ? vW2 : (w == 1) ? cW2 : (w == 2) ? W1 : (w == 3) ? W2 : W3;
    int uw = u & 7;
    int pos = (u & ~7) | ((uw & 3) << 1) | (uw >> 2);
    g_wB[w][nn * PW + pos] = pack_bf16x2(src[(2 * u) * 128 + nn], src[(2 * u + 1) * 128 + nn]);
}

// ---------------------------------------------------------------------------
// mlp2_scatter: 256 rows/CTA. h = relu(f @ W1[2,128]+b1) fp32 -> bf16 tile;
// emb = h@W2+b2 -> scatter bf16x2 words (permuted) to g_xbuf[assoc].
// ---------------------------------------------------------------------------
extern "C" __global__ void __launch_bounds__(512)
mlp2_scatter_kernel(const float* __restrict__ feats, const int* __restrict__ assoc,
                    const float* __restrict__ W1g, const float* __restrict__ b1g,
                    const float* __restrict__ b2g, int n, int widx)
{
    extern __shared__ uint32_t smw[];
    uint32_t* A = smw;                        // 256*PW words
    uint32_t* B = smw + 256 * PW;             // 128*PW words
    float* misc = (float*)(smw + (256 + 128) * PW);
    float* F0  = misc;           // 256
    float* F1  = misc + 256;     // 256
    float* W1s = misc + 512;     // 256
    float* b1s = misc + 768;     // 128
    float* b2s = misc + 896;     // 128
    int*   nodes = (int*)(misc + 1024);   // 256

    const int tid = threadIdx.x, lane = tid & 31, w = tid >> 5;
    const int m0 = blockIdx.x * 256;
    const int m0w = (w & 7) * 32, n0w = (w >> 3) * 64;

    if (tid < 256) {
        W1s[tid] = W1g[tid];
        if (tid < 128) { b1s[tid] = b1g[tid]; b2s[tid] = b2g[tid]; }
        int r = m0 + tid;
        nodes[tid] = (r < n) ? assoc[r] : 0;
        float2 f = (r < n) ? ((const float2*)feats)[r] : make_float2(0.f, 0.f);
        F0[tid] = f.x; F1[tid] = f.y;
    }
    stageB(B, g_wB[widx], tid);
    __syncthreads();

    // Layer 1 (fp32) -> A bf16x2 permuted. One thread = one (row, 16-k chunk).
    for (int idx = tid; idx < 256 * 8; idx += 512) {
        int m = idx >> 3, c = idx & 7, k0 = c * 16;
        float f0 = F0[m], f1 = F1[m];
        uint32_t wv[8];
#pragma unroll
        for (int u = 0; u < 8; u++) {
            int k = k0 + 2 * u;
            float h0 = fmaxf(fmaf(f0, W1s[k],     fmaf(f1, W1s[128 + k],     b1s[k])),     0.f);
            float h1 = fmaxf(fmaf(f0, W1s[k + 1], fmaf(f1, W1s[128 + k + 1], b1s[k + 1])), 0.f);
            wv[u] = pack_bf16x2(h0, h1);
        }
        uint32_t* dst = A + m * PW + c * 8;
        *(uint4*)(dst)     = make_uint4(wv[0], wv[4], wv[1], wv[5]);
        *(uint4*)(dst + 4) = make_uint4(wv[2], wv[6], wv[3], wv[7]);
    }
    __syncthreads();

    float acc[2][8][4];
#pragma unroll
    for (int mt = 0; mt < 2; mt++)
#pragma unroll
        for (int nt = 0; nt < 8; nt++)
#pragma unroll
            for (int c = 0; c < 4; c++) acc[mt][nt][c] = 0.f;

    gemm_frag(A, B, acc, lane, m0w, n0w);

    // Epilogue: +b2, pack bf16x2 permuted, scatter to g_xbuf.
    const int g = lane >> 2, tg = lane & 3;
#pragma unroll
    for (int mt = 0; mt < 2; mt++) {
        int row0 = m0w + 16 * mt + g;
        int row1 = row0 + 8;
        bool v0 = (m0 + row0 < n), v1 = (m0 + row1 < n);
        uint32_t* d0 = g_xbuf + (size_t)nodes[row0] * 64;
        uint32_t* d1 = g_xbuf + (size_t)nodes[row1] * 64;
#pragma unroll
        for (int q = 0; q < 4; q++) {
            int colA = n0w + 16 * q + 2 * tg;        // j = 2q
            int colB = colA + 8;                     // j = 2q+1
            int wpos = n0w / 2 + 8 * q + 2 * tg;
            if (v0) {
                uint2 pv;
                pv.x = pack_bf16x2(acc[mt][2*q][0]   + b2s[colA], acc[mt][2*q][1]   + b2s[colA+1]);
                pv.y = pack_bf16x2(acc[mt][2*q+1][0] + b2s[colB], acc[mt][2*q+1][1] + b2s[colB+1]);
                *(uint2*)(d0 + wpos) = pv;
            }
            if (v1) {
                uint2 pv;
                pv.x = pack_bf16x2(acc[mt][2*q][2]   + b2s[colA], acc[mt][2*q][3]   + b2s[colA+1]);
                pv.y = pack_bf16x2(acc[mt][2*q+1][2] + b2s[colB], acc[mt][2*q+1][3] + b2s[colB+1]);
                *(uint2*)(d1 + wpos) = pv;
            }
        }
    }
}

// ---------------------------------------------------------------------------
// head: 256 rows/CTA. gather (straight copy, already permuted) ->
// 3x (GEMM+bias+ReLU) -> dot W4 + b4 -> sigmoid.
// ---------------------------------------------------------------------------
extern "C" __global__ void __launch_bounds__(512)
head_kernel(const int* __restrict__ assoc,
            const float* __restrict__ b1g, const float* __restrict__ b2g,
            const float* __restrict__ b3g, const float* __restrict__ W4g,
            const float* __restrict__ b4g, float* __restrict__ out, int n)
{
    extern __shared__ uint32_t smw[];
    uint32_t* A = smw;
    uint32_t* B = smw + 256 * PW;
    float* misc = (float*)(smw + (256 + 128) * PW);
    // misc: [0]b1 [128]b2 [256]b3 [384]W4 [512]part(512) [1024]nodes(int 256)
    float* W4s  = misc + 384;
    float* part = misc + 512;
    int*   nodes = (int*)(misc + 1024);

    const int tid = threadIdx.x, lane = tid & 31, w = tid >> 5;
    const int m0 = blockIdx.x * 256;
    const int m0w = (w & 7) * 32, n0w = (w >> 3) * 64;
    const int g = lane >> 2, tg = lane & 3;

    if (tid < 256) {
        if (tid < 128) {
            misc[tid]       = b1g[tid];
            misc[128 + tid] = b2g[tid];
            misc[256 + tid] = b3g[tid];
            W4s[tid]        = W4g[tid];
        }
        int r = m0 + tid;
        nodes[tid] = (r < n) ? assoc[r] : 0;
    }
    __syncthreads();

    // Gather -> A (words already permuted in g_xbuf).
    for (int idx = tid; idx < 256 * 16; idx += 512) {
        int m = idx >> 4, q = idx & 15;
        uint4 v = *(const uint4*)(g_xbuf + (size_t)nodes[m] * 64 + q * 4);
        *(uint4*)(A + m * PW + q * 4) = v;
    }
    stageB(B, g_wB[2], tid);
    __syncthreads();

#pragma unroll 1
    for (int lyr = 0; lyr < 3; lyr++) {
        float acc[2][8][4];
#pragma unroll
        for (int mt = 0; mt < 2; mt++)
#pragma unroll
            for (int nt = 0; nt < 8; nt++)
#pragma unroll
                for (int c = 0; c < 4; c++) acc[mt][nt][c] = 0.f;

        gemm_frag(A, B, acc, lane, m0w, n0w);
        __syncthreads();   // all warps done reading A and B

        const float* bias = misc + lyr * 128;
        if (lyr < 2) {
            // relu + bias + pack -> A in place (permuted words), restage B.
#pragma unroll
            for (int mt = 0; mt < 2; mt++) {
                int row0 = m0w + 16 * mt + g;
                uint32_t* a0 = A + row0 * PW;
                uint32_t* a1 = A + (row0 + 8) * PW;
#pragma unroll
                for (int q = 0; q < 4; q++) {
                    int colA = n0w + 16 * q + 2 * tg;
                    int colB = colA + 8;
                    int wpos = n0w / 2 + 8 * q + 2 * tg;
                    uint2 p0, p1;
                    p0.x = pack_bf16x2(fmaxf(acc[mt][2*q][0]   + bias[colA], 0.f),
                                       fmaxf(acc[mt][2*q][1]   + bias[colA+1], 0.f));
                    p0.y = pack_bf16x2(fmaxf(acc[mt][2*q+1][0] + bias[colB], 0.f),
                                       fmaxf(acc[mt][2*q+1][1] + bias[colB+1], 0.f));
                    p1.x = pack_bf16x2(fmaxf(acc[mt][2*q][2]   + bias[colA], 0.f),
                                       fmaxf(acc[mt][2*q][3]   + bias[colA+1], 0.f));
                    p1.y = pack_bf16x2(fmaxf(acc[mt][2*q+1][2] + bias[colB], 0.f),
                                       fmaxf(acc[mt][2*q+1][3] + bias[colB+1], 0.f));
                    *(uint2*)(a0 + wpos) = p0;
                    *(uint2*)(a1 + wpos) = p1;
                }
            }
            stageB(B, g_wB[3 + lyr], tid);
            __syncthreads();
        } else {
            // Final: relu + bias, dot with W4, reduce 4-lane group.
#pragma unroll
            for (int mt = 0; mt < 2; mt++) {
                float p0 = 0.f, p1 = 0.f;
#pragma unroll
                for (int j = 0; j < 8; j++) {
                    int col = n0w + 8 * j + 2 * tg;
                    p0 = fmaf(fmaxf(acc[mt][j][0] + bias[col], 0.f),     W4s[col],     p0);
                    p0 = fmaf(fmaxf(acc[mt][j][1] + bias[col + 1], 0.f), W4s[col + 1], p0);
                    p1 = fmaf(fmaxf(acc[mt][j][2] + bias[col], 0.f),     W4s[col],     p1);
                    p1 = fmaf(fmaxf(acc[mt][j][3] + bias[col + 1], 0.f), W4s[col + 1], p1);
                }
                p0 += __shfl_xor_sync(0xffffffffu, p0, 1);
                p0 += __shfl_xor_sync(0xffffffffu, p0, 2);
                p1 += __shfl_xor_sync(0xffffffffu, p1, 1);
                p1 += __shfl_xor_sync(0xffffffffu, p1, 2);
                if (tg == 0) {
                    int row0 = m0w + 16 * mt + g;
                    part[(w >> 3) * 256 + row0]     = p0;
                    part[(w >> 3) * 256 + row0 + 8] = p1;
                }
            }
            __syncthreads();
            if (tid < 256) {
                int row = m0 + tid;
                if (row < n) {
                    float s = part[tid] + part[256 + tid] + __ldg(&b4g[0]);
                    out[row] = 1.f / (1.f + expf(-s));
                }
            }
        }
    }
}

// ---------------------------------------------------------------------------
// Launch
// ---------------------------------------------------------------------------
extern "C" void kernel_launch(void* const* d_in, const int* in_sizes, int n_in,
                              void* d_out, int out_size)
{
    (void)n_in; (void)out_size;
    const float* varf      = (const float*)d_in[0];
    const float* conf      = (const float*)d_in[1];
    const int*   assoc_var = (const int*)d_in[3];
    const int*   assoc_con = (const int*)d_in[4];
    const float* vW1 = (const float*)d_in[5];
    const float* vb1 = (const float*)d_in[6];
    const float* vW2 = (const float*)d_in[7];
    const float* vb2 = (const float*)d_in[8];
    const float* cW1 = (const float*)d_in[9];
    const float* cb1 = (const float*)d_in[10];
    const float* cW2 = (const float*)d_in[11];
    const float* cb2 = (const float*)d_in[12];
    const float* W1  = (const float*)d_in[13];
    const float* b1  = (const float*)d_in[14];
    const float* W2  = (const float*)d_in[15];
    const float* b2  = (const float*)d_in[16];
    const float* W3  = (const float*)d_in[17];
    const float* b3  = (const float*)d_in[18];
    const float* W4  = (const float*)d_in[19];
    const float* b4  = (const float*)d_in[20];
    float* out = (float*)d_out;

    const int n_var = in_sizes[0] / 2;
    const int n_con = in_sizes[1] / 2;

    // A(256*72 w) + B(128*72 w) + misc(1280 fl + 256 int) ≈ 116 KB
    const int smem_bytes = ((256 + 128) * PW + 1280 + 256) * 4 + 1024;

    cudaFuncSetAttribute(mlp2_scatter_kernel,
                         cudaFuncAttributeMaxDynamicSharedMemorySize, smem_bytes);
    cudaFuncSetAttribute(head_kernel,
                         cudaFuncAttributeMaxDynamicSharedMemorySize, smem_bytes);

    const int gv = (n_var + 255) / 256;
    const int gc = (n_con + 255) / 256;

    prep_kernel<<<(5 * 128 * 64 + 255) / 256, 256>>>(vW2, cW2, W1, W2, W3);
    // var first, con second (con overwrites shared nodes), then head.
    mlp2_scatter_kernel<<<gv, 512, smem_bytes>>>(varf, assoc_var, vW1, vb1, vb2, n_var, 0);
    mlp2_scatter_kernel<<<gc, 512, smem_bytes>>>(conf, assoc_con, cW1, cb1, cb2, n_con, 1);
    head_kernel<<<gv, 512, smem_bytes>>>(assoc_var, b1, b2, b3, W4, b4, out, n_var);
}

// round 9
// speedup vs baseline: 5.7510x; 1.4065x over previous
#include <cuda_runtime.h>
#include <cuda_bf16.h>
#include <math.h>
#include <stdint.h>

// ---------------------------------------------------------------------------
// Net_76690936037575 — bf16 mma.sync (m16n8k16), M=128 tiles, 256 threads,
// 2 CTAs/SM (independent barrier domains overlap tensor + epilogue phases).
// SMEM tiles hold bf16x2 words, k-permuted so every mma fragment load is one
// uint2 (8B) LDS. g_xbuf holds node embeddings as bf16, pre-permuted.
// Dead-work elimination: var rows whose node is overwritten by the con
// scatter are skipped (mask built from assoc_con each call).
// All scalar math (layer-1, bias, ReLU, sigmoid, W4-dot) stays fp32.
// ---------------------------------------------------------------------------

#define PW 72   // words (bf16x2) per tile row: 64 data + 8 pad

// Node embeddings: 1e6 nodes x 64 words (128 bf16), permuted layout. 256 MB.
__device__ uint32_t g_xbuf[64u * 1000000u];
// Transposed + permuted bf16x2 weights: 0=vW2^T 1=cW2^T 2=W1^T 3=W2^T 4=W3^T
__device__ uint32_t g_wB[5][128 * PW];
// mask[node] = 1 if node is written by the con scatter (var write is dead).
__device__ unsigned char g_mask[1000000u];

__device__ __forceinline__ uint32_t pack_bf16x2(float lo, float hi) {
    uint32_t r;
    asm("cvt.rn.bf16x2.f32 %0, %1, %2;" : "=r"(r) : "f"(hi), "f"(lo));
    return r;
}

__device__ __forceinline__ void mma16(float* d, const uint32_t* a, const uint32_t* b) {
    asm volatile("mma.sync.aligned.m16n8k16.row.col.f32.bf16.bf16.f32 "
                 "{%0,%1,%2,%3}, {%4,%5,%6,%7}, {%8,%9}, {%0,%1,%2,%3};"
                 : "+f"(d[0]), "+f"(d[1]), "+f"(d[2]), "+f"(d[3])
                 : "r"(a[0]), "r"(a[1]), "r"(a[2]), "r"(a[3]),
                   "r"(b[0]), "r"(b[1]));
}

// Warp GEMM 32m x 64n x 128k over permuted bf16x2 word tiles.
__device__ __forceinline__ void gemm_frag(const uint32_t* __restrict__ As,
                                          const uint32_t* __restrict__ Bs,
                                          float acc[2][8][4],
                                          int lane, int m0w, int n0w)
{
    const int g = lane >> 2, tg = lane & 3;
    const uint32_t* Ab = As + (m0w + g) * PW + 2 * tg;
    const uint32_t* Bb = Bs + (n0w + g) * PW + 2 * tg;
#pragma unroll
    for (int kt = 0; kt < 8; kt++) {
        const int k0 = kt * 8;   // words
        uint2 a00 = *(const uint2*)(Ab + k0);
        uint2 a01 = *(const uint2*)(Ab + 8 * PW + k0);
        uint2 a10 = *(const uint2*)(Ab + 16 * PW + k0);
        uint2 a11 = *(const uint2*)(Ab + 24 * PW + k0);
        uint32_t a[2][4];
        a[0][0] = a00.x; a[0][1] = a01.x; a[0][2] = a00.y; a[0][3] = a01.y;
        a[1][0] = a10.x; a[1][1] = a11.x; a[1][2] = a10.y; a[1][3] = a11.y;
        uint32_t b[8][2];
#pragma unroll
        for (int nt = 0; nt < 8; nt++) {
            uint2 bv = *(const uint2*)(Bb + nt * 8 * PW + k0);
            b[nt][0] = bv.x; b[nt][1] = bv.y;
        }
#pragma unroll
        for (int mt = 0; mt < 2; mt++)
#pragma unroll
            for (int nt = 0; nt < 8; nt++)
                mma16(acc[mt][nt], a[mt], b[nt]);
    }
}

__device__ __forceinline__ void stageB(uint32_t* __restrict__ Bs,
                                       const uint32_t* __restrict__ wt, int tid)
{
    const uint4* src = (const uint4*)wt;
    uint4* dst = (uint4*)Bs;
#pragma unroll 3
    for (int i = tid; i < 128 * PW / 4; i += 256) dst[i] = src[i];
}

// ---------------------------------------------------------------------------
// Prep: g_wB[w][n*PW + (u&~7) + p(u&7)] = bf16x2(W[2u][n], W[2u+1][n]).
// ---------------------------------------------------------------------------
extern "C" __global__ void prep_kernel(const float* __restrict__ vW2, const float* __restrict__ cW2,
                                       const float* __restrict__ W1, const float* __restrict__ W2,
                                       const float* __restrict__ W3)
{
    int idx = blockIdx.x * 256 + threadIdx.x;
    if (idx >= 5 * 128 * 64) return;
    int w = idx >> 13, e = idx & 8191;
    int nn = e >> 6, u = e & 63;
    const float* src = (w == 0) ? vW2 : (w == 1) ? cW2 : (w == 2) ? W1 : (w == 3) ? W2 : W3;
    int uw = u & 7;
    int pos = (u & ~7) | ((uw & 3) << 1) | (uw >> 2);
    g_wB[w][nn * PW + pos] = pack_bf16x2(src[(2 * u) * 128 + nn], src[(2 * u + 1) * 128 + nn]);
}

// Mark nodes that the con scatter will write (var writes there are dead).
extern "C" __global__ void mark_kernel(const int* __restrict__ assoc_con, int n)
{
    int i = blockIdx.x * 256 + threadIdx.x;
    if (i < n) g_mask[assoc_con[i]] = 1;
}

// ---------------------------------------------------------------------------
// mlp2_scatter: 128 rows/CTA. h = relu(f @ W1[2,128]+b1) fp32 -> bf16 tile;
// emb = h@W2+b2 -> scatter bf16x2 words (permuted) to g_xbuf[assoc].
// If maskp != 0, rows whose node is masked are dead; all-dead CTAs exit.
// ---------------------------------------------------------------------------
extern "C" __global__ void __launch_bounds__(256, 2)
mlp2_scatter_kernel(const float* __restrict__ feats, const int* __restrict__ assoc,
                    const float* __restrict__ W1g, const float* __restrict__ b1g,
                    const float* __restrict__ b2g,
                    const unsigned char* __restrict__ maskp, int n, int widx)
{
    extern __shared__ uint32_t smw[];
    uint32_t* A = smw;                        // 128*PW
    uint32_t* B = smw + 128 * PW;             // 128*PW
    float* misc = (float*)(smw + 2 * 128 * PW);
    float* F0  = misc;           // 128
    float* F1  = misc + 128;     // 128
    float* W1s = misc + 256;     // 256
    float* b1s = misc + 512;     // 128
    float* b2s = misc + 640;     // 128
    int*   nodes = (int*)(misc + 768);    // 128
    int*   sdead = (int*)(misc + 896);    // 128

    const int tid = threadIdx.x, lane = tid & 31, w = tid >> 5;
    const int m0 = blockIdx.x * 128;
    const int m0w = (w & 3) * 32, n0w = (w >> 2) * 64;

    int mydead = 1;
    if (tid < 128) {
        int r = m0 + tid;
        int nd = (r < n) ? assoc[r] : 0;
        nodes[tid] = nd;
        mydead = (r < n) ? (maskp ? (int)maskp[nd] : 0) : 1;
        sdead[tid] = mydead;
    }
    if (__syncthreads_and(mydead)) return;   // whole tile dead

    if (tid < 256) W1s[tid] = W1g[tid];
    if (tid < 128) {
        b1s[tid] = b1g[tid];
        b2s[tid] = b2g[tid];
        int r = m0 + tid;
        float2 f = (r < n) ? ((const float2*)feats)[r] : make_float2(0.f, 0.f);
        F0[tid] = f.x; F1[tid] = f.y;
    }
    stageB(B, g_wB[widx], tid);
    __syncthreads();

    // Layer 1 (fp32) -> A bf16x2 permuted. One thread = one (row, 16-k chunk).
    for (int idx = tid; idx < 128 * 8; idx += 256) {
        int m = idx >> 3, c = idx & 7, k0 = c * 16;
        float f0 = F0[m], f1 = F1[m];
        uint32_t wv[8];
#pragma unroll
        for (int u = 0; u < 8; u++) {
            int k = k0 + 2 * u;
            float h0 = fmaxf(fmaf(f0, W1s[k],     fmaf(f1, W1s[128 + k],     b1s[k])),     0.f);
            float h1 = fmaxf(fmaf(f0, W1s[k + 1], fmaf(f1, W1s[128 + k + 1], b1s[k + 1])), 0.f);
            wv[u] = pack_bf16x2(h0, h1);
        }
        uint32_t* dst = A + m * PW + c * 8;
        *(uint4*)(dst)     = make_uint4(wv[0], wv[4], wv[1], wv[5]);
        *(uint4*)(dst + 4) = make_uint4(wv[2], wv[6], wv[3], wv[7]);
    }
    __syncthreads();

    float acc[2][8][4];
#pragma unroll
    for (int mt = 0; mt < 2; mt++)
#pragma unroll
        for (int nt = 0; nt < 8; nt++)
#pragma unroll
            for (int c = 0; c < 4; c++) acc[mt][nt][c] = 0.f;

    gemm_frag(A, B, acc, lane, m0w, n0w);

    // Epilogue: +b2, pack bf16x2 permuted, scatter live rows to g_xbuf.
    const int g = lane >> 2, tg = lane & 3;
#pragma unroll
    for (int mt = 0; mt < 2; mt++) {
        int row0 = m0w + 16 * mt + g;
        int row1 = row0 + 8;
        bool v0 = (m0 + row0 < n) && !sdead[row0];
        bool v1 = (m0 + row1 < n) && !sdead[row1];
        uint32_t* d0 = g_xbuf + (size_t)nodes[row0] * 64;
        uint32_t* d1 = g_xbuf + (size_t)nodes[row1] * 64;
#pragma unroll
        for (int q = 0; q < 4; q++) {
            int colA = n0w + 16 * q + 2 * tg;        // j = 2q
            int colB = colA + 8;                     // j = 2q+1
            int wpos = n0w / 2 + 8 * q + 2 * tg;
            if (v0) {
                uint2 pv;
                pv.x = pack_bf16x2(acc[mt][2*q][0]   + b2s[colA], acc[mt][2*q][1]   + b2s[colA+1]);
                pv.y = pack_bf16x2(acc[mt][2*q+1][0] + b2s[colB], acc[mt][2*q+1][1] + b2s[colB+1]);
                *(uint2*)(d0 + wpos) = pv;
            }
            if (v1) {
                uint2 pv;
                pv.x = pack_bf16x2(acc[mt][2*q][2]   + b2s[colA], acc[mt][2*q][3]   + b2s[colA+1]);
                pv.y = pack_bf16x2(acc[mt][2*q+1][2] + b2s[colB], acc[mt][2*q+1][3] + b2s[colB+1]);
                *(uint2*)(d1 + wpos) = pv;
            }
        }
    }
}

// ---------------------------------------------------------------------------
// head: 128 rows/CTA, 256 threads, 2 CTAs/SM. gather (straight copy) ->
// 3x (GEMM+bias+ReLU) -> dot W4 + b4 -> sigmoid.
// ---------------------------------------------------------------------------
extern "C" __global__ void __launch_bounds__(256, 2)
head_kernel(const int* __restrict__ assoc,
            const float* __restrict__ b1g, const float* __restrict__ b2g,
            const float* __restrict__ b3g, const float* __restrict__ W4g,
            const float* __restrict__ b4g, float* __restrict__ out, int n)
{
    extern __shared__ uint32_t smw[];
    uint32_t* A = smw;
    uint32_t* B = smw + 128 * PW;
    float* misc = (float*)(smw + 2 * 128 * PW);
    // misc: [0]b1 [128]b2 [256]b3 [384]W4 [512]part(256) [768]nodes(int 128)
    float* W4s  = misc + 384;
    float* part = misc + 512;
    int*   nodes = (int*)(misc + 768);

    const int tid = threadIdx.x, lane = tid & 31, w = tid >> 5;
    const int m0 = blockIdx.x * 128;
    const int m0w = (w & 3) * 32, n0w = (w >> 2) * 64;
    const int g = lane >> 2, tg = lane & 3;

    if (tid < 128) {
        misc[tid]       = b1g[tid];
        misc[128 + tid] = b2g[tid];
        misc[256 + tid] = b3g[tid];
        W4s[tid]        = W4g[tid];
        int r = m0 + tid;
        nodes[tid] = (r < n) ? assoc[r] : 0;
    }
    __syncthreads();

    // Gather -> A (words already permuted in g_xbuf).
    for (int idx = tid; idx < 128 * 16; idx += 256) {
        int m = idx >> 4, q = idx & 15;
        uint4 v = *(const uint4*)(g_xbuf + (size_t)nodes[m] * 64 + q * 4);
        *(uint4*)(A + m * PW + q * 4) = v;
    }
    stageB(B, g_wB[2], tid);
    __syncthreads();

#pragma unroll 1
    for (int lyr = 0; lyr < 3; lyr++) {
        float acc[2][8][4];
#pragma unroll
        for (int mt = 0; mt < 2; mt++)
#pragma unroll
            for (int nt = 0; nt < 8; nt++)
#pragma unroll
                for (int c = 0; c < 4; c++) acc[mt][nt][c] = 0.f;

        gemm_frag(A, B, acc, lane, m0w, n0w);
        __syncthreads();   // all warps done reading A and B

        const float* bias = misc + lyr * 128;
        if (lyr < 2) {
            // relu + bias + pack -> A in place (permuted words), restage B.
#pragma unroll
            for (int mt = 0; mt < 2; mt++) {
                int row0 = m0w + 16 * mt + g;
                uint32_t* a0 = A + row0 * PW;
                uint32_t* a1 = A + (row0 + 8) * PW;
#pragma unroll
                for (int q = 0; q < 4; q++) {
                    int colA = n0w + 16 * q + 2 * tg;
                    int colB = colA + 8;
                    int wpos = n0w / 2 + 8 * q + 2 * tg;
                    uint2 p0, p1;
                    p0.x = pack_bf16x2(fmaxf(acc[mt][2*q][0]   + bias[colA], 0.f),
                                       fmaxf(acc[mt][2*q][1]   + bias[colA+1], 0.f));
                    p0.y = pack_bf16x2(fmaxf(acc[mt][2*q+1][0] + bias[colB], 0.f),
                                       fmaxf(acc[mt][2*q+1][1] + bias[colB+1], 0.f));
                    p1.x = pack_bf16x2(fmaxf(acc[mt][2*q][2]   + bias[colA], 0.f),
                                       fmaxf(acc[mt][2*q][3]   + bias[colA+1], 0.f));
                    p1.y = pack_bf16x2(fmaxf(acc[mt][2*q+1][2] + bias[colB], 0.f),
                                       fmaxf(acc[mt][2*q+1][3] + bias[colB+1], 0.f));
                    *(uint2*)(a0 + wpos) = p0;
                    *(uint2*)(a1 + wpos) = p1;
                }
            }
            stageB(B, g_wB[3 + lyr], tid);
            __syncthreads();
        } else {
            // Final: relu + bias, dot with W4, reduce 4-lane group.
#pragma unroll
            for (int mt = 0; mt < 2; mt++) {
                float p0 = 0.f, p1 = 0.f;
#pragma unroll
                for (int j = 0; j < 8; j++) {
                    int col = n0w + 8 * j + 2 * tg;
                    p0 = fmaf(fmaxf(acc[mt][j][0] + bias[col], 0.f),     W4s[col],     p0);
                    p0 = fmaf(fmaxf(acc[mt][j][1] + bias[col + 1], 0.f), W4s[col + 1], p0);
                    p1 = fmaf(fmaxf(acc[mt][j][2] + bias[col], 0.f),     W4s[col],     p1);
                    p1 = fmaf(fmaxf(acc[mt][j][3] + bias[col + 1], 0.f), W4s[col + 1], p1);
                }
                p0 += __shfl_xor_sync(0xffffffffu, p0, 1);
                p0 += __shfl_xor_sync(0xffffffffu, p0, 2);
                p1 += __shfl_xor_sync(0xffffffffu, p1, 1);
                p1 += __shfl_xor_sync(0xffffffffu, p1, 2);
                if (tg == 0) {
                    int row0 = m0w + 16 * mt + g;
                    part[(w >> 2) * 128 + row0]     = p0;
                    part[(w >> 2) * 128 + row0 + 8] = p1;
                }
            }
            __syncthreads();
            if (tid < 128) {
                int row = m0 + tid;
                if (row < n) {
                    float s = part[tid] + part[128 + tid] + __ldg(&b4g[0]);
                    out[row] = 1.f / (1.f + expf(-s));
                }
            }
        }
    }
}

// ---------------------------------------------------------------------------
// Launch
// ---------------------------------------------------------------------------
extern "C" void kernel_launch(void* const* d_in, const int* in_sizes, int n_in,
                              void* d_out, int out_size)
{
    (void)n_in; (void)out_size;
    const float* varf      = (const float*)d_in[0];
    const float* conf      = (const float*)d_in[1];
    const int*   assoc_var = (const int*)d_in[3];
    const int*   assoc_con = (const int*)d_in[4];
    const float* vW1 = (const float*)d_in[5];
    const float* vb1 = (const float*)d_in[6];
    const float* vW2 = (const float*)d_in[7];
    const float* vb2 = (const float*)d_in[8];
    const float* cW1 = (const float*)d_in[9];
    const float* cb1 = (const float*)d_in[10];
    const float* cW2 = (const float*)d_in[11];
    const float* cb2 = (const float*)d_in[12];
    const float* W1  = (const float*)d_in[13];
    const float* b1  = (const float*)d_in[14];
    const float* W2  = (const float*)d_in[15];
    const float* b2  = (const float*)d_in[16];
    const float* W3  = (const float*)d_in[17];
    const float* b3  = (const float*)d_in[18];
    const float* W4  = (const float*)d_in[19];
    const float* b4  = (const float*)d_in[20];
    float* out = (float*)d_out;

    const int n_var = in_sizes[0] / 2;
    const int n_con = in_sizes[1] / 2;

    // A(128*72) + B(128*72) + misc ≈ 78 KB per CTA -> 2 CTAs/SM.
    const int smem_bytes = (2 * 128 * PW + 1024) * 4 + 256;

    cudaFuncSetAttribute(mlp2_scatter_kernel,
                         cudaFuncAttributeMaxDynamicSharedMemorySize, smem_bytes);
    cudaFuncSetAttribute(head_kernel,
                         cudaFuncAttributeMaxDynamicSharedMemorySize, smem_bytes);

    unsigned char* mask_dev = nullptr;
    cudaGetSymbolAddress((void**)&mask_dev, g_mask);

    const int gv = (n_var + 127) / 128;
    const int gc = (n_con + 127) / 128;

    prep_kernel<<<(5 * 128 * 64 + 255) / 256, 256>>>(vW2, cW2, W1, W2, W3);
    mark_kernel<<<(n_con + 255) / 256, 256>>>(assoc_con, n_con);
    // var first (dead rows skipped), con second (overwrites), then head.
    mlp2_scatter_kernel<<<gv, 256, smem_bytes>>>(varf, assoc_var, vW1, vb1, vb2, mask_dev, n_var, 0);
    mlp2_scatter_kernel<<<gc, 256, smem_bytes>>>(conf, assoc_con, cW1, cb1, cb2, nullptr, n_con, 1);
    head_kernel<<<gv, 256, smem_bytes>>>(assoc_var, b1, b2, b3, W4, b4, out, n_var);
}